// round 2
// baseline (speedup 1.0000x reference)
#include <cuda_runtime.h>

// Problem constants
#define HH 256
#define WW 256
#define CC 64      // content/blur channels, also output channels of deform conv
#define BB 4
#define OC 18      // offset channels actually used
#define OCP 20     // padded to multiple of 4 for float4 accumulation
#define HW (HH*WW)

// ---------------------------------------------------------------------------
// Kernel A: 3x3 conv, pad 1: blur(4,64,256,256) x offset_w(27->18,64,3,3) -> offset(4,18,256,256)
// One thread per pixel, all 18 output channels in registers (padded to 20).
// Weights in static smem, o-contiguous for broadcast float4 LDS.
// ---------------------------------------------------------------------------
__global__ __launch_bounds__(256, 4)
void offset_conv_kernel(const float* __restrict__ blur,
                        const float* __restrict__ ow,   // (27,64,3,3)
                        const float* __restrict__ ob,   // (27,)
                        float* __restrict__ off_out)    // (4,18,256,256)
{
    __shared__ float ws[CC * 9 * OCP];   // [c][k][o_padded], 46,080 B

    const int tid = threadIdx.x;
    // cooperative weight load: ws[(c*9+k)*OCP + o] = ow[o*(64*9) + c*9 + k]
    for (int i = tid; i < CC * 9 * OCP; i += blockDim.x) {
        int o  = i % OCP;
        int ck = i / OCP;           // c*9 + k
        ws[i] = (o < OC) ? ow[o * (CC * 9) + ck] : 0.0f;
    }
    __syncthreads();

    const int p = blockIdx.x * blockDim.x + tid;   // grid exactly covers B*H*W
    const int x = p & (WW - 1);
    const int y = (p >> 8) & (HH - 1);
    const int b = p >> 16;

    float4 acc[OCP / 4];
#pragma unroll
    for (int j = 0; j < OCP / 4; j++) acc[j] = make_float4(0.f, 0.f, 0.f, 0.f);

    const float* bp = blur + (size_t)b * CC * HW;

    for (int c = 0; c < CC; c++) {
        const float* cp = bp + c * HW;
#pragma unroll
        for (int k = 0; k < 9; k++) {
            const int ky = k / 3 - 1;
            const int kx = k % 3 - 1;
            const int iy = y + ky;
            const int ix = x + kx;
            float v = 0.0f;
            if (iy >= 0 && iy < HH && ix >= 0 && ix < WW)
                v = __ldg(cp + iy * WW + ix);
            const float4* w4 = reinterpret_cast<const float4*>(ws + (c * 9 + k) * OCP);
#pragma unroll
            for (int j = 0; j < OCP / 4; j++) {
                float4 wv = w4[j];
                acc[j].x = fmaf(v, wv.x, acc[j].x);
                acc[j].y = fmaf(v, wv.y, acc[j].y);
                acc[j].z = fmaf(v, wv.z, acc[j].z);
                acc[j].w = fmaf(v, wv.w, acc[j].w);
            }
        }
    }

    // write 18 channels (+bias)
    const float* a = reinterpret_cast<const float*>(acc);
    float* op = off_out + ((size_t)b * OC) * HW + y * WW + x;
#pragma unroll
    for (int o = 0; o < OC; o++) {
        op[o * HW] = a[o] + __ldg(ob + o);
    }
}

// ---------------------------------------------------------------------------
// Kernel B: deformable conv. One thread per pixel, 64 fp32 accumulators.
// For each of 9 kernel taps: read (off_y, off_x), bilinear-gather 4 corners
// per input channel from content (L2-resident), FMA into 64 outputs with
// per-k weight slice staged in 16 KB smem (broadcast float4 reads).
// ---------------------------------------------------------------------------
__global__ __launch_bounds__(256, 2)
void deform_conv_kernel(const float* __restrict__ content,
                        const float* __restrict__ offset,  // (4,18,256,256)
                        const float* __restrict__ dw,      // (64,64,3,3)
                        const float* __restrict__ db,      // (64,)
                        float* __restrict__ out)           // (4,64,256,256)
{
    __shared__ float ws[CC * CC];   // [c][o] for current k, 16 KB

    const int tid = threadIdx.x;
    const int p = blockIdx.x * blockDim.x + tid;
    const int x = p & (WW - 1);
    const int y = (p >> 8) & (HH - 1);
    const int b = p >> 16;

    float4 acc[CC / 4];
#pragma unroll
    for (int j = 0; j < CC / 4; j++) acc[j] = make_float4(0.f, 0.f, 0.f, 0.f);

    const float* cb   = content + (size_t)b * CC * HW;
    const float* offb = offset + (size_t)b * OC * HW + y * WW + x;

    for (int k = 0; k < 9; k++) {
        __syncthreads();
        // ws[c*64+o] = dw[o*64*9 + c*9 + k]; coalesced STS, scattered L2-hit LDG
        for (int i = tid; i < CC * CC; i += blockDim.x) {
            int c = i >> 6;
            int o = i & 63;
            ws[i] = __ldg(dw + (o * CC + c) * 9 + k);
        }
        __syncthreads();

        const float offy = __ldg(offb + (2 * k) * HW);
        const float offx = __ldg(offb + (2 * k + 1) * HW);
        const float py = (float)(y + (k / 3) - 1) + offy;
        const float px = (float)(x + (k % 3) - 1) + offx;

        const float y0f = floorf(py);
        const float x0f = floorf(px);
        const float wy = py - y0f;
        const float wx = px - x0f;
        const int iy0 = (int)y0f, ix0 = (int)x0f;
        const int iy1 = iy0 + 1,  ix1 = ix0 + 1;

        const bool vy0 = (iy0 >= 0) && (iy0 < HH);
        const bool vy1 = (iy1 >= 0) && (iy1 < HH);
        const bool vx0 = (ix0 >= 0) && (ix0 < WW);
        const bool vx1 = (ix1 >= 0) && (ix1 < WW);

        const float w00 = (1.f - wy) * (1.f - wx) * ((vy0 && vx0) ? 1.f : 0.f);
        const float w01 = (1.f - wy) * wx         * ((vy0 && vx1) ? 1.f : 0.f);
        const float w10 = wy * (1.f - wx)         * ((vy1 && vx0) ? 1.f : 0.f);
        const float w11 = wy * wx                 * ((vy1 && vx1) ? 1.f : 0.f);

        const int cy0 = min(max(iy0, 0), HH - 1);
        const int cy1 = min(max(iy1, 0), HH - 1);
        const int cx0 = min(max(ix0, 0), WW - 1);
        const int cx1 = min(max(ix1, 0), WW - 1);

        const int i00 = cy0 * WW + cx0;
        const int i01 = cy0 * WW + cx1;
        const int i10 = cy1 * WW + cx0;
        const int i11 = cy1 * WW + cx1;

#pragma unroll 2
        for (int c = 0; c < CC; c++) {
            const float* cp = cb + c * HW;
            const float samp = w00 * __ldg(cp + i00)
                             + w01 * __ldg(cp + i01)
                             + w10 * __ldg(cp + i10)
                             + w11 * __ldg(cp + i11);
            const float4* w4 = reinterpret_cast<const float4*>(ws + c * CC);
#pragma unroll
            for (int j = 0; j < CC / 4; j++) {
                float4 wv = w4[j];
                acc[j].x = fmaf(samp, wv.x, acc[j].x);
                acc[j].y = fmaf(samp, wv.y, acc[j].y);
                acc[j].z = fmaf(samp, wv.z, acc[j].z);
                acc[j].w = fmaf(samp, wv.w, acc[j].w);
            }
        }
    }

    // write 64 output channels (+bias)
    const float* a = reinterpret_cast<const float*>(acc);
    float* op = out + (size_t)b * CC * HW + y * WW + x;
#pragma unroll
    for (int o = 0; o < CC; o++) {
        op[o * HW] = a[o] + __ldg(db + o);
    }
}

// ---------------------------------------------------------------------------
// kernel_launch: inputs per metadata order:
//   d_in[0] content_feats (4,64,256,256) f32
//   d_in[1] blur_feats    (4,64,256,256) f32
//   d_in[2] offset_w      (27,64,3,3)    f32
//   d_in[3] offset_b      (27,)          f32
//   d_in[4] dc_w          (64,64,3,3)    f32
//   d_in[5] dc_b          (64,)          f32
// d_out = [ out (4,64,256,256) | offset (4,18,256,256) ]
// ---------------------------------------------------------------------------
extern "C" void kernel_launch(void* const* d_in, const int* in_sizes, int n_in,
                              void* d_out, int out_size)
{
    const float* content = (const float*)d_in[0];
    const float* blur    = (const float*)d_in[1];
    const float* ow      = (const float*)d_in[2];
    const float* ob      = (const float*)d_in[3];
    const float* dw      = (const float*)d_in[4];
    const float* db      = (const float*)d_in[5];

    float* out     = (float*)d_out;
    float* off_out = out + (size_t)BB * CC * HW;   // offset region of output

    const int threads = 256;
    const int blocks = (BB * HW) / threads;        // 1024

    offset_conv_kernel<<<blocks, threads>>>(blur, ow, ob, off_out);
    deform_conv_kernel<<<blocks, threads>>>(content, off_out, dw, db, out);
}